// round 1
// baseline (speedup 1.0000x reference)
#include <cuda_runtime.h>
#include <cstdint>

#define BB 16
#define TT 8
#define CC 1024
#define SPAST 8192
#define SS 8200
#define BT 128
#define NCHUNK 33
#define CHUNK 256
#define SCALE 0.03125f   // 1024^-0.5

// ---------------- scratch (device globals; no runtime alloc) ----------------
__device__ float g_q[BT * CC];                                  // 0.5 MB
__device__ float g_att[(size_t)BB * SS * TT];                   // [b][s][t] 4.2 MB
__device__ float g_rsum[BT];
__device__ float g_part[(size_t)BB * NCHUNK * TT * CC];         // 17.3 MB
__device__ float g_ctx[BT * CC];

// ---------------- pass 0: qkv = x @ w_qkv + b_qkv ----------------
// grid 48 (64-col tiles of N=3072), 256 threads
__global__ void k_qkv(const float* __restrict__ x, const float* __restrict__ w,
                      const float* __restrict__ bias,
                      float* __restrict__ out_k, float* __restrict__ out_v) {
    __shared__ float xs[BT * 32];
    int tid = threadIdx.x;
    int tx = tid & 63, ty = tid >> 6;
    int n = blockIdx.x * 64 + tx;
    float acc[32];
#pragma unroll
    for (int r = 0; r < 32; r++) acc[r] = 0.f;
    for (int kc = 0; kc < CC; kc += 32) {
        __syncthreads();
        for (int i = tid; i < BT * 32; i += 256) {
            int row = i >> 5, kk = i & 31;
            xs[i] = x[row * CC + kc + kk];
        }
        __syncthreads();
#pragma unroll 8
        for (int kk = 0; kk < 32; kk++) {
            float wv = w[(size_t)(kc + kk) * 3072 + n];
#pragma unroll
            for (int r = 0; r < 32; r++)
                acc[r] += xs[(ty * 32 + r) * 32 + kk] * wv;
        }
    }
    float bv = bias[n];
#pragma unroll
    for (int r = 0; r < 32; r++) {
        int row = ty * 32 + r;
        int b = row >> 3, t = row & 7;
        float v = acc[r] + bv;
        if (n < CC)
            g_q[row * CC + n] = v;
        else if (n < 2 * CC)
            out_k[((size_t)b * SS + SPAST + t) * CC + (n - CC)] = v;
        else
            out_v[((size_t)b * SS + SPAST + t) * CC + (n - 2 * CC)] = v;
    }
}

// ---------------- pass 1: fused K-copy + logits ----------------
// grid (33, 16), 256 threads. Each warp: 2 rows at a time, 8 q-dot accumulators.
__global__ void k_attnK(const float* __restrict__ cache_k, float* __restrict__ out_k) {
    __shared__ float sq[TT * CC];   // 32 KB: q for this batch
    int tid = threadIdx.x;
    int b = blockIdx.y;
    int s0 = blockIdx.x * CHUNK;
    int nrows = min(CHUNK, SS - s0);
    const float4* qsrc = (const float4*)(g_q + (size_t)b * TT * CC);
    float4* sq4 = (float4*)sq;
    for (int i = tid; i < TT * CC / 4; i += 256) sq4[i] = qsrc[i];
    __syncthreads();

    int w = tid >> 5, l = tid & 31;
    for (int rb = w * 2; rb < nrows; rb += 16) {
        int sA = s0 + rb, sB = sA + 1;
        bool cpA = sA < SPAST, cpB = sB < SPAST;
        const float4* KA = cpA ? (const float4*)(cache_k + ((size_t)b * SPAST + sA) * CC)
                               : (const float4*)(out_k + ((size_t)b * SS + sA) * CC);
        const float4* KB = cpB ? (const float4*)(cache_k + ((size_t)b * SPAST + sB) * CC)
                               : (const float4*)(out_k + ((size_t)b * SS + sB) * CC);
        float4* OA = (float4*)(out_k + ((size_t)b * SS + sA) * CC);
        float4* OB = (float4*)(out_k + ((size_t)b * SS + sB) * CC);
        float accA[8], accB[8];
#pragma unroll
        for (int t = 0; t < 8; t++) { accA[t] = 0.f; accB[t] = 0.f; }
#pragma unroll
        for (int j = 0; j < 8; j++) {
            int ci = j * 32 + l;
            float4 ka = __ldcs(KA + ci);
            float4 kb = __ldcs(KB + ci);
            if (cpA) __stcs(OA + ci, ka);
            if (cpB) __stcs(OB + ci, kb);
#pragma unroll
            for (int t = 0; t < 8; t++) {
                float4 qv = sq4[t * 256 + ci];
                accA[t] += ka.x * qv.x + ka.y * qv.y + ka.z * qv.z + ka.w * qv.w;
                accB[t] += kb.x * qv.x + kb.y * qv.y + kb.z * qv.z + kb.w * qv.w;
            }
        }
#pragma unroll
        for (int t = 0; t < 8; t++) {
#pragma unroll
            for (int off = 16; off > 0; off >>= 1) {
                accA[t] += __shfl_down_sync(0xffffffffu, accA[t], off);
                accB[t] += __shfl_down_sync(0xffffffffu, accB[t], off);
            }
        }
        if (l == 0) {
            float4* dA = (float4*)(g_att + ((size_t)b * SS + sA) * TT);
            float4* dB = (float4*)(g_att + ((size_t)b * SS + sB) * TT);
            dA[0] = make_float4(accA[0] * SCALE, accA[1] * SCALE, accA[2] * SCALE, accA[3] * SCALE);
            dA[1] = make_float4(accA[4] * SCALE, accA[5] * SCALE, accA[6] * SCALE, accA[7] * SCALE);
            dB[0] = make_float4(accB[0] * SCALE, accB[1] * SCALE, accB[2] * SCALE, accB[3] * SCALE);
            dB[1] = make_float4(accB[4] * SCALE, accB[5] * SCALE, accB[6] * SCALE, accB[7] * SCALE);
        }
    }
}

// ---------------- pass 2: softmax (store exp(x-max) + reciprocal sums) ----------------
// grid 16 (one CTA per batch), 256 threads
__global__ void k_softmax() {
    int b = blockIdx.x, tid = threadIdx.x;
    int w = tid >> 5, l = tid & 31;
    float4* att4 = (float4*)(g_att + (size_t)b * SS * TT);
    __shared__ float red[64];
    __shared__ float fin[8];

    float m[8];
#pragma unroll
    for (int t = 0; t < 8; t++) m[t] = -1e30f;
    for (int s = tid; s < SS; s += 256) {
        float4 a0 = att4[s * 2], a1 = att4[s * 2 + 1];
        m[0] = fmaxf(m[0], a0.x); m[1] = fmaxf(m[1], a0.y);
        m[2] = fmaxf(m[2], a0.z); m[3] = fmaxf(m[3], a0.w);
        m[4] = fmaxf(m[4], a1.x); m[5] = fmaxf(m[5], a1.y);
        m[6] = fmaxf(m[6], a1.z); m[7] = fmaxf(m[7], a1.w);
    }
#pragma unroll
    for (int t = 0; t < 8; t++)
#pragma unroll
        for (int off = 16; off > 0; off >>= 1)
            m[t] = fmaxf(m[t], __shfl_xor_sync(0xffffffffu, m[t], off));
    if (l == 0)
#pragma unroll
        for (int t = 0; t < 8; t++) red[w * 8 + t] = m[t];
    __syncthreads();
    if (tid < 8) {
        float mm = red[tid];
#pragma unroll
        for (int ww = 1; ww < 8; ww++) mm = fmaxf(mm, red[ww * 8 + tid]);
        fin[tid] = mm;
    }
    __syncthreads();
    float lm[8];
#pragma unroll
    for (int t = 0; t < 8; t++) lm[t] = fin[t];

    float sum[8];
#pragma unroll
    for (int t = 0; t < 8; t++) sum[t] = 0.f;
    for (int s = tid; s < SS; s += 256) {
        float4 a0 = att4[s * 2], a1 = att4[s * 2 + 1];
        a0.x = __expf(a0.x - lm[0]); a0.y = __expf(a0.y - lm[1]);
        a0.z = __expf(a0.z - lm[2]); a0.w = __expf(a0.w - lm[3]);
        a1.x = __expf(a1.x - lm[4]); a1.y = __expf(a1.y - lm[5]);
        a1.z = __expf(a1.z - lm[6]); a1.w = __expf(a1.w - lm[7]);
        sum[0] += a0.x; sum[1] += a0.y; sum[2] += a0.z; sum[3] += a0.w;
        sum[4] += a1.x; sum[5] += a1.y; sum[6] += a1.z; sum[7] += a1.w;
        att4[s * 2] = a0; att4[s * 2 + 1] = a1;
    }
#pragma unroll
    for (int t = 0; t < 8; t++)
#pragma unroll
        for (int off = 16; off > 0; off >>= 1)
            sum[t] += __shfl_xor_sync(0xffffffffu, sum[t], off);
    __syncthreads();
    if (l == 0)
#pragma unroll
        for (int t = 0; t < 8; t++) red[w * 8 + t] = sum[t];
    __syncthreads();
    if (tid < 8) {
        float ss = 0.f;
#pragma unroll
        for (int ww = 0; ww < 8; ww++) ss += red[ww * 8 + tid];
        g_rsum[b * 8 + tid] = 1.0f / ss;
    }
}

// ---------------- pass 3: fused V-copy + ctx partials ----------------
// grid (33, 16), 256 threads. Thread owns a float4 column slice (1024 cols).
__global__ void k_attnV(const float* __restrict__ cache_v, float* __restrict__ out_v) {
    __shared__ float sp[CHUNK * TT];   // 8 KB prob tile [i][t]
    int tid = threadIdx.x;
    int b = blockIdx.y;
    int chunk = blockIdx.x;
    int s0 = chunk * CHUNK;
    int nrows = min(CHUNK, SS - s0);
    const float4* psrc = (const float4*)(g_att + ((size_t)b * SS + s0) * TT);
    float4* sp4 = (float4*)sp;
    for (int i = tid; i < nrows * 2; i += 256) sp4[i] = psrc[i];
    __syncthreads();

    float4 acc[8];
#pragma unroll
    for (int t = 0; t < 8; t++) acc[t] = make_float4(0.f, 0.f, 0.f, 0.f);

#pragma unroll 2
    for (int i = 0; i < nrows; i++) {
        int s = s0 + i;
        bool cp = s < SPAST;
        const float4* V = cp ? (const float4*)(cache_v + ((size_t)b * SPAST + s) * CC)
                             : (const float4*)(out_v + ((size_t)b * SS + s) * CC);
        float4 vv = __ldcs(V + tid);
        if (cp) __stcs((float4*)(out_v + ((size_t)b * SS + s) * CC) + tid, vv);
        float4 p0 = sp4[i * 2], p1 = sp4[i * 2 + 1];
        acc[0].x += vv.x * p0.x; acc[0].y += vv.y * p0.x; acc[0].z += vv.z * p0.x; acc[0].w += vv.w * p0.x;
        acc[1].x += vv.x * p0.y; acc[1].y += vv.y * p0.y; acc[1].z += vv.z * p0.y; acc[1].w += vv.w * p0.y;
        acc[2].x += vv.x * p0.z; acc[2].y += vv.y * p0.z; acc[2].z += vv.z * p0.z; acc[2].w += vv.w * p0.z;
        acc[3].x += vv.x * p0.w; acc[3].y += vv.y * p0.w; acc[3].z += vv.z * p0.w; acc[3].w += vv.w * p0.w;
        acc[4].x += vv.x * p1.x; acc[4].y += vv.y * p1.x; acc[4].z += vv.z * p1.x; acc[4].w += vv.w * p1.x;
        acc[5].x += vv.x * p1.y; acc[5].y += vv.y * p1.y; acc[5].z += vv.z * p1.y; acc[5].w += vv.w * p1.y;
        acc[6].x += vv.x * p1.z; acc[6].y += vv.y * p1.z; acc[6].z += vv.z * p1.z; acc[6].w += vv.w * p1.z;
        acc[7].x += vv.x * p1.w; acc[7].y += vv.y * p1.w; acc[7].z += vv.z * p1.w; acc[7].w += vv.w * p1.w;
    }
    float4* dst = (float4*)(g_part + ((size_t)(b * NCHUNK + chunk) * TT) * CC);
#pragma unroll
    for (int t = 0; t < 8; t++) dst[t * 256 + tid] = acc[t];
}

// ---------------- pass 4a: reduce chunk partials -> ctx ----------------
// grid 512, 256 threads
__global__ void k_reduce() {
    int gid = blockIdx.x * 256 + threadIdx.x;   // 0..131071
    int row = gid >> 10, c = gid & 1023;
    int b = row >> 3, t = row & 7;
    float s = 0.f;
#pragma unroll
    for (int ch = 0; ch < NCHUNK; ch++)
        s += g_part[((size_t)(b * NCHUNK + ch) * TT + t) * CC + c];
    g_ctx[gid] = s * g_rsum[row];
}

// ---------------- pass 4b: out = ctx @ w_out + b_out ----------------
// grid 16 (64-col tiles of N=1024), 256 threads
__global__ void k_out(const float* __restrict__ w, const float* __restrict__ bias,
                      float* __restrict__ out) {
    __shared__ float xs[BT * 32];
    int tid = threadIdx.x;
    int tx = tid & 63, ty = tid >> 6;
    int n = blockIdx.x * 64 + tx;
    float acc[32];
#pragma unroll
    for (int r = 0; r < 32; r++) acc[r] = 0.f;
    for (int kc = 0; kc < CC; kc += 32) {
        __syncthreads();
        for (int i = tid; i < BT * 32; i += 256) {
            int row = i >> 5, kk = i & 31;
            xs[i] = g_ctx[row * CC + kc + kk];
        }
        __syncthreads();
#pragma unroll 8
        for (int kk = 0; kk < 32; kk++) {
            float wv = w[(size_t)(kc + kk) * CC + n];
#pragma unroll
            for (int r = 0; r < 32; r++)
                acc[r] += xs[(ty * 32 + r) * 32 + kk] * wv;
        }
    }
    float bv = bias[n];
#pragma unroll
    for (int r = 0; r < 32; r++) {
        int row = ty * 32 + r;
        out[row * CC + n] = acc[r] + bv;
    }
}

// ---------------- launch ----------------
extern "C" void kernel_launch(void* const* d_in, const int* in_sizes, int n_in,
                              void* d_out, int out_size) {
    const float* x       = (const float*)d_in[0];
    const float* cache_k = (const float*)d_in[1];
    const float* cache_v = (const float*)d_in[2];
    const float* w_qkv   = (const float*)d_in[3];
    const float* b_qkv   = (const float*)d_in[4];
    const float* w_out   = (const float*)d_in[5];
    const float* b_out   = (const float*)d_in[6];

    float* out_o = (float*)d_out;
    float* out_k = out_o + (size_t)BT * CC;            // after [16,8,1024]
    float* out_v = out_k + (size_t)BB * SS * CC;       // after k [16,8200,1024]

    k_qkv<<<48, 256>>>(x, w_qkv, b_qkv, out_k, out_v);
    k_attnK<<<dim3(NCHUNK, BB), 256>>>(cache_k, out_k);
    k_softmax<<<BB, 256>>>();
    k_attnV<<<dim3(NCHUNK, BB), 256>>>(cache_v, out_v);
    k_reduce<<<512, 256>>>();
    k_out<<<16, 256>>>(w_out, b_out, out_o);
}

// round 2
// speedup vs baseline: 1.1311x; 1.1311x over previous
#include <cuda_runtime.h>
#include <cstdint>

#define BB 16
#define TT 8
#define CC 1024
#define SPAST 8192
#define SS 8200
#define BT 128
#define CHUNK 128
#define NCHUNK 65          // 64 full chunks cover SPAST exactly; chunk 64 = 8 new rows
#define SCALE 0.03125f     // 1024^-0.5

// ---------------- scratch (device globals; no runtime alloc) ----------------
__device__ float g_q[BT * CC];                                   // 0.5 MB
__device__ float g_psum[BB * NCHUNK * TT];                       // per-chunk exp sums
__device__ float g_part[(size_t)BB * NCHUNK * TT * CC];          // 34 MB ctx partials
__device__ float g_ctx[BT * CC];

// ---------------- pass 0: qkv = x @ w_qkv + b_qkv ----------------
// grid (96, 2): 32-col tiles of N=3072, 64-row halves. 256 threads.
__global__ void k_qkv(const float* __restrict__ x, const float* __restrict__ w,
                      const float* __restrict__ bias,
                      float* __restrict__ out_k, float* __restrict__ out_v) {
    __shared__ float xs[64 * 32];
    int tid = threadIdx.x;
    int tx = tid & 31, ty = tid >> 5;          // col lane, row group
    int n = blockIdx.x * 32 + tx;
    int r0 = blockIdx.y * 64;
    float acc[8];
#pragma unroll
    for (int r = 0; r < 8; r++) acc[r] = 0.f;
    for (int kc = 0; kc < CC; kc += 32) {
        __syncthreads();
        for (int i = tid; i < 64 * 32; i += 256) {
            int row = r0 + (i >> 5), kk = i & 31;
            xs[i] = x[row * CC + kc + kk];
        }
        __syncthreads();
#pragma unroll 8
        for (int kk = 0; kk < 32; kk++) {
            float wv = w[(size_t)(kc + kk) * 3072 + n];
#pragma unroll
            for (int r = 0; r < 8; r++)
                acc[r] += xs[(ty * 8 + r) * 32 + kk] * wv;
        }
    }
    float bv = bias[n];
#pragma unroll
    for (int r = 0; r < 8; r++) {
        int row = r0 + ty * 8 + r;
        int b = row >> 3, t = row & 7;
        float v = acc[r] + bv;
        if (n < CC)
            g_q[row * CC + n] = v;
        else if (n < 2 * CC)
            out_k[((size_t)b * SS + SPAST + t) * CC + (n - CC)] = v;
        else
            out_v[((size_t)b * SS + SPAST + t) * CC + (n - 2 * CC)] = v;
    }
}

// ---------------- pass 1: FUSED attention (K copy+logits, exp, V copy+ctx) ----
// grid (65, 16), 256 threads. One CTA = one (batch, 128-row S-chunk).
__global__ __launch_bounds__(256) void k_attn(const float* __restrict__ cache_k,
                                              const float* __restrict__ cache_v,
                                              float* __restrict__ out_k,
                                              float* __restrict__ out_v) {
    __shared__ float sq[TT * CC];      // 32 KB q tile for this batch
    __shared__ float sp[CHUNK * TT];   // 4 KB logits -> probabilities [row][t]
    int tid = threadIdx.x;
    int b = blockIdx.y;
    int chunk = blockIdx.x;
    int s0 = chunk * CHUNK;
    int nrows = min(CHUNK, SS - s0);
    bool cp = (chunk < 64);            // SPAST = 64*CHUNK: copy-side is uniform per CTA

    // load q tile
    const float4* qsrc = (const float4*)(g_q + (size_t)b * TT * CC);
    float4* sq4 = (float4*)sq;
    for (int i = tid; i < TT * CC / 4; i += 256) sq4[i] = qsrc[i];
    __syncthreads();

    int w = tid >> 5, l = tid & 31;

    // ---- phase A: stream K rows: copy to out_k + dot with 8 q rows ----
    const float4* kin = cp ? (const float4*)(cache_k + ((size_t)b * SPAST + s0) * CC)
                           : (const float4*)(out_k + ((size_t)b * SS + s0) * CC);
    float4* kout = (float4*)(out_k + ((size_t)b * SS + s0) * CC);
    for (int rb = w * 2; rb < nrows; rb += 16) {
        const float4* KA = kin + (size_t)rb * 256;
        const float4* KB = kin + (size_t)(rb + 1) * 256;
        float4* OA = kout + (size_t)rb * 256;
        float4* OB = kout + (size_t)(rb + 1) * 256;
        float accA[8], accB[8];
#pragma unroll
        for (int t = 0; t < 8; t++) { accA[t] = 0.f; accB[t] = 0.f; }
#pragma unroll
        for (int j = 0; j < 8; j++) {
            int ci = j * 32 + l;
            float4 ka = __ldcs(KA + ci);
            float4 kb = __ldcs(KB + ci);
            if (cp) { __stcs(OA + ci, ka); __stcs(OB + ci, kb); }
#pragma unroll
            for (int t = 0; t < 8; t++) {
                float4 qv = sq4[t * 256 + ci];
                accA[t] += ka.x * qv.x + ka.y * qv.y + ka.z * qv.z + ka.w * qv.w;
                accB[t] += kb.x * qv.x + kb.y * qv.y + kb.z * qv.z + kb.w * qv.w;
            }
        }
#pragma unroll
        for (int t = 0; t < 8; t++) {
#pragma unroll
            for (int off = 16; off > 0; off >>= 1) {
                accA[t] += __shfl_down_sync(0xffffffffu, accA[t], off);
                accB[t] += __shfl_down_sync(0xffffffffu, accB[t], off);
            }
        }
        if (l == 0) {
            float4* dA = (float4*)(sp + rb * 8);
            dA[0] = make_float4(accA[0] * SCALE, accA[1] * SCALE, accA[2] * SCALE, accA[3] * SCALE);
            dA[1] = make_float4(accA[4] * SCALE, accA[5] * SCALE, accA[6] * SCALE, accA[7] * SCALE);
            float4* dB = (float4*)(sp + (rb + 1) * 8);
            dB[0] = make_float4(accB[0] * SCALE, accB[1] * SCALE, accB[2] * SCALE, accB[3] * SCALE);
            dB[1] = make_float4(accB[4] * SCALE, accB[5] * SCALE, accB[6] * SCALE, accB[7] * SCALE);
        }
    }
    __syncthreads();

    // ---- phase B: exp in-place + per-chunk per-t sums (warps 0..7, col = w) ----
    if (w < 8) {
        float s = 0.f;
        for (int r = l; r < nrows; r += 32) {
            float e = __expf(sp[r * 8 + w]);
            sp[r * 8 + w] = e;
            s += e;
        }
#pragma unroll
        for (int off = 16; off > 0; off >>= 1)
            s += __shfl_down_sync(0xffffffffu, s, off);
        if (l == 0) g_psum[(b * NCHUNK + chunk) * TT + w] = s;
    }
    __syncthreads();

    // ---- phase C: stream V rows: copy to out_v + accumulate p*V ----
    const float4* vin = cp ? (const float4*)(cache_v + ((size_t)b * SPAST + s0) * CC)
                           : (const float4*)(out_v + ((size_t)b * SS + s0) * CC);
    float4* vout = (float4*)(out_v + ((size_t)b * SS + s0) * CC);
    float4* sp4 = (float4*)sp;

    float4 acc[8];
#pragma unroll
    for (int t = 0; t < 8; t++) acc[t] = make_float4(0.f, 0.f, 0.f, 0.f);

#pragma unroll 2
    for (int i = 0; i < nrows; i += 4) {
        float4 vr[4];
        vr[0] = __ldcs(vin + (size_t)(i + 0) * 256 + tid);
        vr[1] = __ldcs(vin + (size_t)(i + 1) * 256 + tid);
        vr[2] = __ldcs(vin + (size_t)(i + 2) * 256 + tid);
        vr[3] = __ldcs(vin + (size_t)(i + 3) * 256 + tid);
        if (cp) {
            __stcs(vout + (size_t)(i + 0) * 256 + tid, vr[0]);
            __stcs(vout + (size_t)(i + 1) * 256 + tid, vr[1]);
            __stcs(vout + (size_t)(i + 2) * 256 + tid, vr[2]);
            __stcs(vout + (size_t)(i + 3) * 256 + tid, vr[3]);
        }
#pragma unroll
        for (int r = 0; r < 4; r++) {
            float4 vv = vr[r];
            float4 p0 = sp4[(i + r) * 2], p1 = sp4[(i + r) * 2 + 1];
            acc[0].x += vv.x * p0.x; acc[0].y += vv.y * p0.x; acc[0].z += vv.z * p0.x; acc[0].w += vv.w * p0.x;
            acc[1].x += vv.x * p0.y; acc[1].y += vv.y * p0.y; acc[1].z += vv.z * p0.y; acc[1].w += vv.w * p0.y;
            acc[2].x += vv.x * p0.z; acc[2].y += vv.y * p0.z; acc[2].z += vv.z * p0.z; acc[2].w += vv.w * p0.z;
            acc[3].x += vv.x * p0.w; acc[3].y += vv.y * p0.w; acc[3].z += vv.z * p0.w; acc[3].w += vv.w * p0.w;
            acc[4].x += vv.x * p1.x; acc[4].y += vv.y * p1.x; acc[4].z += vv.z * p1.x; acc[4].w += vv.w * p1.x;
            acc[5].x += vv.x * p1.y; acc[5].y += vv.y * p1.y; acc[5].z += vv.z * p1.y; acc[5].w += vv.w * p1.y;
            acc[6].x += vv.x * p1.z; acc[6].y += vv.y * p1.z; acc[6].z += vv.z * p1.z; acc[6].w += vv.w * p1.z;
            acc[7].x += vv.x * p1.w; acc[7].y += vv.y * p1.w; acc[7].z += vv.z * p1.w; acc[7].w += vv.w * p1.w;
        }
    }
    float4* dst = (float4*)(g_part + ((size_t)(b * NCHUNK + chunk) * TT) * CC);
#pragma unroll
    for (int t = 0; t < 8; t++) dst[t * 256 + tid] = acc[t];
}

// ---------------- pass 2: reduce chunk partials -> normalized ctx ----------------
// grid 512, 256 threads
__global__ void k_reduce() {
    int gid = blockIdx.x * 256 + threadIdx.x;   // 0..131071
    int row = gid >> 10, c = gid & 1023;
    int b = row >> 3, t = row & 7;
    float S = 0.f;
#pragma unroll
    for (int ch = 0; ch < NCHUNK; ch++)
        S += g_psum[(b * NCHUNK + ch) * TT + t];
    float s = 0.f;
#pragma unroll
    for (int ch = 0; ch < NCHUNK; ch++)
        s += g_part[((size_t)(b * NCHUNK + ch) * TT + t) * CC + c];
    g_ctx[gid] = s * (1.0f / S);
}

// ---------------- pass 3: out = ctx @ w_out + b_out ----------------
// grid (32, 2): 32-col tiles of N=1024, 64-row halves. 256 threads.
__global__ void k_out(const float* __restrict__ w, const float* __restrict__ bias,
                      float* __restrict__ out) {
    __shared__ float xs[64 * 32];
    int tid = threadIdx.x;
    int tx = tid & 31, ty = tid >> 5;
    int n = blockIdx.x * 32 + tx;
    int r0 = blockIdx.y * 64;
    float acc[8];
#pragma unroll
    for (int r = 0; r < 8; r++) acc[r] = 0.f;
    for (int kc = 0; kc < CC; kc += 32) {
        __syncthreads();
        for (int i = tid; i < 64 * 32; i += 256) {
            int row = r0 + (i >> 5), kk = i & 31;
            xs[i] = g_ctx[row * CC + kc + kk];
        }
        __syncthreads();
#pragma unroll 8
        for (int kk = 0; kk < 32; kk++) {
            float wv = w[(size_t)(kc + kk) * CC + n];
#pragma unroll
            for (int r = 0; r < 8; r++)
                acc[r] += xs[(ty * 8 + r) * 32 + kk] * wv;
        }
    }
    float bv = bias[n];
#pragma unroll
    for (int r = 0; r < 8; r++) {
        int row = r0 + ty * 8 + r;
        out[row * CC + n] = acc[r] + bv;
    }
}

// ---------------- launch ----------------
extern "C" void kernel_launch(void* const* d_in, const int* in_sizes, int n_in,
                              void* d_out, int out_size) {
    const float* x       = (const float*)d_in[0];
    const float* cache_k = (const float*)d_in[1];
    const float* cache_v = (const float*)d_in[2];
    const float* w_qkv   = (const float*)d_in[3];
    const float* b_qkv   = (const float*)d_in[4];
    const float* w_out   = (const float*)d_in[5];
    const float* b_out   = (const float*)d_in[6];

    float* out_o = (float*)d_out;
    float* out_k = out_o + (size_t)BT * CC;            // after [16,8,1024]
    float* out_v = out_k + (size_t)BB * SS * CC;       // after k [16,8200,1024]

    k_qkv<<<dim3(96, 2), 256>>>(x, w_qkv, b_qkv, out_k, out_v);
    k_attn<<<dim3(NCHUNK, BB), 256>>>(cache_k, cache_v, out_k, out_v);
    k_reduce<<<512, 256>>>();
    k_out<<<dim3(32, 2), 256>>>(w_out, b_out, out_o);
}

// round 3
// speedup vs baseline: 1.7344x; 1.5334x over previous
#include <cuda_runtime.h>
#include <cstdint>

#define BB 16
#define TT 8
#define CC 1024
#define SPAST 8192
#define SS 8200
#define BT 128
#define CHUNK 128
#define NCHUNK 65          // 64 full chunks cover SPAST exactly; chunk 64 = 8 new rows
#define SCALE 0.03125f     // 1024^-0.5
#define KSPLIT 8
#define KC 128             // K-chunk per CTA in split-K GEMMs

// ---------------- scratch (device globals; no runtime alloc) ----------------
__device__ float g_q[BT * CC];                                   // 0.5 MB
__device__ float g_psum[BB * NCHUNK * TT];                       // per-chunk exp sums
__device__ float g_part[(size_t)BB * NCHUNK * TT * CC];          // 34 MB ctx partials
__device__ float g_ctx[BT * CC];
__device__ float g_qkvp[(size_t)KSPLIT * BT * 3072];             // 12.6 MB qkv split-K partials
__device__ float g_outp[(size_t)KSPLIT * BT * CC];               // 4.2 MB out split-K partials

// ---------------- split-K GEMM: part[ks] = A[M,Kc] x W[Kc,NT] ----------------
// grid (NT/64, M/64, KSPLIT), 256 threads. Thread tile 4 rows x 4 cols.
// BUF: 0 -> g_qkvp (A = param), 1 -> g_outp (A = g_ctx)
template <int NT, int BUF>
__global__ __launch_bounds__(256) void k_gemm(const float* __restrict__ A,
                                              const float* __restrict__ W) {
    __shared__ float xs[64 * 33];
    const float* Ain = (BUF == 0) ? A : g_ctx;
    float* part = (BUF == 0) ? g_qkvp : g_outp;
    int tid = threadIdx.x;
    int cl = tid & 15;                 // col lane -> 4 cols
    int rg = tid >> 4;                 // 0..15 row group -> 4 rows
    int n0 = blockIdx.x * 64 + cl * 4;
    int r0 = blockIdx.y * 64;
    int k0 = blockIdx.z * KC;

    float4 acc[4];
#pragma unroll
    for (int r = 0; r < 4; r++) acc[r] = make_float4(0.f, 0.f, 0.f, 0.f);

    for (int ks = 0; ks < KC; ks += 32) {
        __syncthreads();
        for (int i = tid; i < 64 * 32; i += 256) {
            int row = i >> 5, kk = i & 31;
            xs[row * 33 + kk] = Ain[(size_t)(r0 + row) * CC + k0 + ks + kk];
        }
        __syncthreads();
#pragma unroll
        for (int kk = 0; kk < 32; kk++) {
            float4 wv = *(const float4*)&W[(size_t)(k0 + ks + kk) * NT + n0];
#pragma unroll
            for (int r = 0; r < 4; r++) {
                float a = xs[(rg * 4 + r) * 33 + kk];
                acc[r].x += a * wv.x;
                acc[r].y += a * wv.y;
                acc[r].z += a * wv.z;
                acc[r].w += a * wv.w;
            }
        }
    }
#pragma unroll
    for (int r = 0; r < 4; r++) {
        int row = r0 + rg * 4 + r;
        *(float4*)&part[((size_t)blockIdx.z * BT + row) * NT + n0] = acc[r];
    }
}

// ---------------- qkv reduce: sum 8 partials + bias, scatter to q/k/v ----------
// grid 384, 256 threads (float4 over 128x3072)
__global__ void k_qkv_red(const float* __restrict__ bias,
                          float* __restrict__ out_k, float* __restrict__ out_v) {
    int g4 = blockIdx.x * 256 + threadIdx.x;   // 0..98303
    int row = g4 / 768;
    int n = (g4 - row * 768) * 4;
    float4 s = make_float4(0.f, 0.f, 0.f, 0.f);
#pragma unroll
    for (int ks = 0; ks < KSPLIT; ks++) {
        float4 p = *(const float4*)&g_qkvp[((size_t)ks * BT + row) * 3072 + n];
        s.x += p.x; s.y += p.y; s.z += p.z; s.w += p.w;
    }
    float4 bv = *(const float4*)&bias[n];
    s.x += bv.x; s.y += bv.y; s.z += bv.z; s.w += bv.w;
    int b = row >> 3, t = row & 7;
    if (n < CC)
        *(float4*)&g_q[row * CC + n] = s;
    else if (n < 2 * CC)
        *(float4*)&out_k[((size_t)b * SS + SPAST + t) * CC + (n - CC)] = s;
    else
        *(float4*)&out_v[((size_t)b * SS + SPAST + t) * CC + (n - 2 * CC)] = s;
}

// ---------------- out reduce: sum 8 partials + bias -> d_out ----------------
// grid 128, 256 threads (float4 over 128x1024)
__global__ void k_out_red(const float* __restrict__ bias, float* __restrict__ out) {
    int g4 = blockIdx.x * 256 + threadIdx.x;   // 0..32767
    int row = g4 >> 8;
    int n = (g4 & 255) * 4;
    float4 s = make_float4(0.f, 0.f, 0.f, 0.f);
#pragma unroll
    for (int ks = 0; ks < KSPLIT; ks++) {
        float4 p = *(const float4*)&g_outp[((size_t)ks * BT + row) * CC + n];
        s.x += p.x; s.y += p.y; s.z += p.z; s.w += p.w;
    }
    float4 bv = *(const float4*)&bias[n];
    s.x += bv.x; s.y += bv.y; s.z += bv.z; s.w += bv.w;
    *(float4*)&out[(size_t)row * CC + n] = s;
}

// ---------------- FUSED attention (K copy+logits, exp, V copy+ctx) ----------
// grid (65, 16), 256 threads. One CTA = one (batch, 128-row S-chunk).
__global__ __launch_bounds__(256) void k_attn(const float* __restrict__ cache_k,
                                              const float* __restrict__ cache_v,
                                              float* __restrict__ out_k,
                                              float* __restrict__ out_v) {
    __shared__ float sq[TT * CC];      // 32 KB q tile for this batch
    __shared__ float sp[CHUNK * TT];   // 4 KB logits -> probabilities [row][t]
    int tid = threadIdx.x;
    int b = blockIdx.y;
    int chunk = blockIdx.x;
    int s0 = chunk * CHUNK;
    int nrows = min(CHUNK, SS - s0);
    bool cp = (chunk < 64);            // SPAST = 64*CHUNK: copy-side is uniform per CTA

    const float4* qsrc = (const float4*)(g_q + (size_t)b * TT * CC);
    float4* sq4 = (float4*)sq;
    for (int i = tid; i < TT * CC / 4; i += 256) sq4[i] = qsrc[i];
    __syncthreads();

    int w = tid >> 5, l = tid & 31;

    // ---- phase A: stream K rows: copy to out_k + dot with 8 q rows ----
    const float4* kin = cp ? (const float4*)(cache_k + ((size_t)b * SPAST + s0) * CC)
                           : (const float4*)(out_k + ((size_t)b * SS + s0) * CC);
    float4* kout = (float4*)(out_k + ((size_t)b * SS + s0) * CC);
    for (int rb = w * 2; rb < nrows; rb += 16) {
        const float4* KA = kin + (size_t)rb * 256;
        const float4* KB = kin + (size_t)(rb + 1) * 256;
        float4* OA = kout + (size_t)rb * 256;
        float4* OB = kout + (size_t)(rb + 1) * 256;
        float accA[8], accB[8];
#pragma unroll
        for (int t = 0; t < 8; t++) { accA[t] = 0.f; accB[t] = 0.f; }
#pragma unroll
        for (int j = 0; j < 8; j++) {
            int ci = j * 32 + l;
            float4 ka = __ldcs(KA + ci);
            float4 kb = __ldcs(KB + ci);
            if (cp) { __stcs(OA + ci, ka); __stcs(OB + ci, kb); }
#pragma unroll
            for (int t = 0; t < 8; t++) {
                float4 qv = sq4[t * 256 + ci];
                accA[t] += ka.x * qv.x + ka.y * qv.y + ka.z * qv.z + ka.w * qv.w;
                accB[t] += kb.x * qv.x + kb.y * qv.y + kb.z * qv.z + kb.w * qv.w;
            }
        }
#pragma unroll
        for (int t = 0; t < 8; t++) {
#pragma unroll
            for (int off = 16; off > 0; off >>= 1) {
                accA[t] += __shfl_down_sync(0xffffffffu, accA[t], off);
                accB[t] += __shfl_down_sync(0xffffffffu, accB[t], off);
            }
        }
        if (l == 0) {
            float4* dA = (float4*)(sp + rb * 8);
            dA[0] = make_float4(accA[0] * SCALE, accA[1] * SCALE, accA[2] * SCALE, accA[3] * SCALE);
            dA[1] = make_float4(accA[4] * SCALE, accA[5] * SCALE, accA[6] * SCALE, accA[7] * SCALE);
            float4* dB = (float4*)(sp + (rb + 1) * 8);
            dB[0] = make_float4(accB[0] * SCALE, accB[1] * SCALE, accB[2] * SCALE, accB[3] * SCALE);
            dB[1] = make_float4(accB[4] * SCALE, accB[5] * SCALE, accB[6] * SCALE, accB[7] * SCALE);
        }
    }
    __syncthreads();

    // ---- phase B: exp in-place + per-chunk per-t sums ----
    if (w < 8) {
        float s = 0.f;
        for (int r = l; r < nrows; r += 32) {
            float e = __expf(sp[r * 8 + w]);
            sp[r * 8 + w] = e;
            s += e;
        }
#pragma unroll
        for (int off = 16; off > 0; off >>= 1)
            s += __shfl_down_sync(0xffffffffu, s, off);
        if (l == 0) g_psum[(b * NCHUNK + chunk) * TT + w] = s;
    }
    __syncthreads();

    // ---- phase C: stream V rows: copy to out_v + accumulate p*V ----
    const float4* vin = cp ? (const float4*)(cache_v + ((size_t)b * SPAST + s0) * CC)
                           : (const float4*)(out_v + ((size_t)b * SS + s0) * CC);
    float4* vout = (float4*)(out_v + ((size_t)b * SS + s0) * CC);
    float4* sp4 = (float4*)sp;

    float4 acc[8];
#pragma unroll
    for (int t = 0; t < 8; t++) acc[t] = make_float4(0.f, 0.f, 0.f, 0.f);

#pragma unroll 2
    for (int i = 0; i < nrows; i += 4) {
        float4 vr[4];
        vr[0] = __ldcs(vin + (size_t)(i + 0) * 256 + tid);
        vr[1] = __ldcs(vin + (size_t)(i + 1) * 256 + tid);
        vr[2] = __ldcs(vin + (size_t)(i + 2) * 256 + tid);
        vr[3] = __ldcs(vin + (size_t)(i + 3) * 256 + tid);
        if (cp) {
            __stcs(vout + (size_t)(i + 0) * 256 + tid, vr[0]);
            __stcs(vout + (size_t)(i + 1) * 256 + tid, vr[1]);
            __stcs(vout + (size_t)(i + 2) * 256 + tid, vr[2]);
            __stcs(vout + (size_t)(i + 3) * 256 + tid, vr[3]);
        }
#pragma unroll
        for (int r = 0; r < 4; r++) {
            float4 vv = vr[r];
            float4 p0 = sp4[(i + r) * 2], p1 = sp4[(i + r) * 2 + 1];
            acc[0].x += vv.x * p0.x; acc[0].y += vv.y * p0.x; acc[0].z += vv.z * p0.x; acc[0].w += vv.w * p0.x;
            acc[1].x += vv.x * p0.y; acc[1].y += vv.y * p0.y; acc[1].z += vv.z * p0.y; acc[1].w += vv.w * p0.y;
            acc[2].x += vv.x * p0.z; acc[2].y += vv.y * p0.z; acc[2].z += vv.z * p0.z; acc[2].w += vv.w * p0.z;
            acc[3].x += vv.x * p0.w; acc[3].y += vv.y * p0.w; acc[3].z += vv.z * p0.w; acc[3].w += vv.w * p0.w;
            acc[4].x += vv.x * p1.x; acc[4].y += vv.y * p1.x; acc[4].z += vv.z * p1.x; acc[4].w += vv.w * p1.x;
            acc[5].x += vv.x * p1.y; acc[5].y += vv.y * p1.y; acc[5].z += vv.z * p1.y; acc[5].w += vv.w * p1.y;
            acc[6].x += vv.x * p1.z; acc[6].y += vv.y * p1.z; acc[6].z += vv.z * p1.z; acc[6].w += vv.w * p1.z;
            acc[7].x += vv.x * p1.w; acc[7].y += vv.y * p1.w; acc[7].z += vv.z * p1.w; acc[7].w += vv.w * p1.w;
        }
    }
    float4* dst = (float4*)(g_part + ((size_t)(b * NCHUNK + chunk) * TT) * CC);
#pragma unroll
    for (int t = 0; t < 8; t++) dst[t * 256 + tid] = acc[t];
}

// ---------------- reduce chunk partials -> normalized ctx ----------------
// grid 512, 256 threads
__global__ void k_reduce() {
    int gid = blockIdx.x * 256 + threadIdx.x;   // 0..131071
    int row = gid >> 10, c = gid & 1023;
    int b = row >> 3, t = row & 7;
    float S = 0.f;
#pragma unroll
    for (int ch = 0; ch < NCHUNK; ch++)
        S += g_psum[(b * NCHUNK + ch) * TT + t];
    float s = 0.f;
#pragma unroll
    for (int ch = 0; ch < NCHUNK; ch++)
        s += g_part[((size_t)(b * NCHUNK + ch) * TT + t) * CC + c];
    g_ctx[gid] = s * (1.0f / S);
}

// ---------------- launch ----------------
extern "C" void kernel_launch(void* const* d_in, const int* in_sizes, int n_in,
                              void* d_out, int out_size) {
    const float* x       = (const float*)d_in[0];
    const float* cache_k = (const float*)d_in[1];
    const float* cache_v = (const float*)d_in[2];
    const float* w_qkv   = (const float*)d_in[3];
    const float* b_qkv   = (const float*)d_in[4];
    const float* w_out   = (const float*)d_in[5];
    const float* b_out   = (const float*)d_in[6];

    float* out_o = (float*)d_out;
    float* out_k = out_o + (size_t)BT * CC;            // after [16,8,1024]
    float* out_v = out_k + (size_t)BB * SS * CC;       // after k [16,8200,1024]

    k_gemm<3072, 0><<<dim3(48, 2, KSPLIT), 256>>>(x, w_qkv);
    k_qkv_red<<<384, 256>>>(b_qkv, out_k, out_v);
    k_attn<<<dim3(NCHUNK, BB), 256>>>(cache_k, cache_v, out_k, out_v);
    k_reduce<<<512, 256>>>();
    k_gemm<1024, 1><<<dim3(16, 2, KSPLIT), 256>>>(nullptr, w_out);
    k_out_red<<<128, 256>>>(b_out, out_o);
}

// round 5
// speedup vs baseline: 1.8004x; 1.0381x over previous
#include <cuda_runtime.h>
#include <cstdint>

#define BB 16
#define TT 8
#define CC 1024
#define SPAST 8192
#define SS 8200
#define BT 128
#define CHUNK 128
#define NCHUNK 65          // 64 full chunks cover SPAST; chunk 64 = 8 new rows
#define NPOS (BB * NCHUNK) // 1040 work items
#define SCALE 0.03125f     // 1024^-0.5
#define KSPLIT 8
#define KC 128
#define ATTN_GRID 592      // 148 SMs x 4

// ---------------- scratch ----------------
__device__ float g_q[BT * CC];
__device__ float g_psum[BB * NCHUNK * TT];
__device__ float g_part[(size_t)BB * NCHUNK * TT * CC];          // 34 MB
__device__ float g_ctx[BT * CC];
__device__ float g_qkvp[(size_t)KSPLIT * BT * 3072];
__device__ float g_outp[(size_t)KSPLIT * BT * CC];
__device__ unsigned g_ticket;

__global__ void k_reset() { g_ticket = 0; }

// ---------------- split-K GEMM: part[ks] = A[M,Kc] x W[Kc,NT] ----------------
template <int NT, int BUF>
__global__ __launch_bounds__(256) void k_gemm(const float* __restrict__ A,
                                              const float* __restrict__ W) {
    __shared__ float xs[64 * 33];
    const float* Ain = (BUF == 0) ? A : g_ctx;
    float* part = (BUF == 0) ? g_qkvp : g_outp;
    int tid = threadIdx.x;
    int cl = tid & 15;
    int rg = tid >> 4;
    int n0 = blockIdx.x * 64 + cl * 4;
    int r0 = blockIdx.y * 64;
    int k0 = blockIdx.z * KC;

    float4 acc[4];
#pragma unroll
    for (int r = 0; r < 4; r++) acc[r] = make_float4(0.f, 0.f, 0.f, 0.f);

    for (int ks = 0; ks < KC; ks += 32) {
        __syncthreads();
        for (int i = tid; i < 64 * 32; i += 256) {
            int row = i >> 5, kk = i & 31;
            xs[row * 33 + kk] = Ain[(size_t)(r0 + row) * CC + k0 + ks + kk];
        }
        __syncthreads();
#pragma unroll
        for (int kk = 0; kk < 32; kk++) {
            float4 wv = *(const float4*)&W[(size_t)(k0 + ks + kk) * NT + n0];
#pragma unroll
            for (int r = 0; r < 4; r++) {
                float a = xs[(rg * 4 + r) * 33 + kk];
                acc[r].x += a * wv.x;
                acc[r].y += a * wv.y;
                acc[r].z += a * wv.z;
                acc[r].w += a * wv.w;
            }
        }
    }
#pragma unroll
    for (int r = 0; r < 4; r++) {
        int row = r0 + rg * 4 + r;
        *(float4*)&part[((size_t)blockIdx.z * BT + row) * NT + n0] = acc[r];
    }
}

// ---------------- qkv reduce: sum partials + bias, scatter to q/k/v ----------
__global__ void k_qkv_red(const float* __restrict__ bias,
                          float* __restrict__ out_k, float* __restrict__ out_v) {
    int g4 = blockIdx.x * 256 + threadIdx.x;   // 0..98303
    int row = g4 / 768;
    int n = (g4 - row * 768) * 4;
    float4 s = make_float4(0.f, 0.f, 0.f, 0.f);
#pragma unroll
    for (int ks = 0; ks < KSPLIT; ks++) {
        float4 p = *(const float4*)&g_qkvp[((size_t)ks * BT + row) * 3072 + n];
        s.x += p.x; s.y += p.y; s.z += p.z; s.w += p.w;
    }
    float4 bv = *(const float4*)&bias[n];
    s.x += bv.x; s.y += bv.y; s.z += bv.z; s.w += bv.w;
    int b = row >> 3, t = row & 7;
    if (n < CC)
        *(float4*)&g_q[row * CC + n] = s;
    else if (n < 2 * CC)
        *(float4*)&out_k[((size_t)b * SS + SPAST + t) * CC + (n - CC)] = s;
    else
        *(float4*)&out_v[((size_t)b * SS + SPAST + t) * CC + (n - 2 * CC)] = s;
}

// ---------------- out reduce ----------------
__global__ void k_out_red(const float* __restrict__ bias, float* __restrict__ out) {
    int g4 = blockIdx.x * 256 + threadIdx.x;
    int row = g4 >> 8;
    int n = (g4 & 255) * 4;
    float4 s = make_float4(0.f, 0.f, 0.f, 0.f);
#pragma unroll
    for (int ks = 0; ks < KSPLIT; ks++) {
        float4 p = *(const float4*)&g_outp[((size_t)ks * BT + row) * CC + n];
        s.x += p.x; s.y += p.y; s.z += p.z; s.w += p.w;
    }
    float4 bv = *(const float4*)&bias[n];
    s.x += bv.x; s.y += bv.y; s.z += bv.z; s.w += bv.w;
    *(float4*)&out[(size_t)row * CC + n] = s;
}

// ---------------- persistent FUSED attention ----------
__global__ __launch_bounds__(256) void k_attn(const float* __restrict__ cache_k,
                                              const float* __restrict__ cache_v,
                                              float* __restrict__ out_k,
                                              float* __restrict__ out_v) {
    __shared__ float sq[TT * CC];      // 32 KB q tile (current batch)
    __shared__ float sp[CHUNK * TT];   // 4 KB probs [row][t]
    __shared__ int s_pos;
    int tid = threadIdx.x;
    int w = tid >> 5, l = tid & 31;
    float4* sq4 = (float4*)sq;
    float4* sp4 = (float4*)sp;
    int cur_b = -1;

    while (true) {
        if (tid == 0) s_pos = (int)atomicAdd(&g_ticket, 1u);
        __syncthreads();
        int pos = s_pos;
        if (pos >= NPOS) break;
        int b = pos / NCHUNK;
        int chunk = pos - b * NCHUNK;
        int s0 = chunk * CHUNK;
        int nrows = (chunk < 64) ? CHUNK : (SS - 64 * CHUNK);   // 128 or 8
        bool cp = (chunk < 64);

        if (b != cur_b) {
            const float4* qsrc = (const float4*)(g_q + (size_t)b * TT * CC);
            for (int i = tid; i < TT * CC / 4; i += 256) sq4[i] = qsrc[i];
            cur_b = b;
        }
        __syncthreads();

        // ---- phase A: stream K rows (4-row blocks): copy + logits ----
        const float4* kin = cp ? (const float4*)(cache_k + ((size_t)b * SPAST + s0) * CC)
                               : (const float4*)(out_k + ((size_t)b * SS + s0) * CC);
        float4* kout = (float4*)(out_k + ((size_t)b * SS + s0) * CC);
        for (int rb = w * 4; rb < nrows; rb += 32) {
            float acc[4][8];
#pragma unroll
            for (int r = 0; r < 4; r++)
#pragma unroll
                for (int t = 0; t < 8; t++) acc[r][t] = 0.f;
#pragma unroll
            for (int j = 0; j < 8; j++) {
                int ci = j * 32 + l;
                float4 k0 = __ldcs(kin + (size_t)(rb + 0) * 256 + ci);
                float4 k1 = __ldcs(kin + (size_t)(rb + 1) * 256 + ci);
                float4 k2 = __ldcs(kin + (size_t)(rb + 2) * 256 + ci);
                float4 k3 = __ldcs(kin + (size_t)(rb + 3) * 256 + ci);
                if (cp) {
                    __stcs(kout + (size_t)(rb + 0) * 256 + ci, k0);
                    __stcs(kout + (size_t)(rb + 1) * 256 + ci, k1);
                    __stcs(kout + (size_t)(rb + 2) * 256 + ci, k2);
                    __stcs(kout + (size_t)(rb + 3) * 256 + ci, k3);
                }
#pragma unroll
                for (int t = 0; t < 8; t++) {
                    float4 qv = sq4[t * 256 + ci];
                    acc[0][t] += k0.x * qv.x + k0.y * qv.y + k0.z * qv.z + k0.w * qv.w;
                    acc[1][t] += k1.x * qv.x + k1.y * qv.y + k1.z * qv.z + k1.w * qv.w;
                    acc[2][t] += k2.x * qv.x + k2.y * qv.y + k2.z * qv.z + k2.w * qv.w;
                    acc[3][t] += k3.x * qv.x + k3.y * qv.y + k3.z * qv.z + k3.w * qv.w;
                }
            }
#pragma unroll
            for (int r = 0; r < 4; r++)
#pragma unroll
                for (int t = 0; t < 8; t++)
#pragma unroll
                    for (int off = 16; off > 0; off >>= 1)
                        acc[r][t] += __shfl_down_sync(0xffffffffu, acc[r][t], off);
            if (l == 0) {
#pragma unroll
                for (int r = 0; r < 4; r++) {
                    float4* d = (float4*)(sp + (rb + r) * 8);
                    d[0] = make_float4(acc[r][0] * SCALE, acc[r][1] * SCALE,
                                       acc[r][2] * SCALE, acc[r][3] * SCALE);
                    d[1] = make_float4(acc[r][4] * SCALE, acc[r][5] * SCALE,
                                       acc[r][6] * SCALE, acc[r][7] * SCALE);
                }
            }
        }
        __syncthreads();

        // ---- phase B: exp in-place + per-chunk per-t sums ----
        if (w < 8) {
            float s = 0.f;
            for (int r = l; r < nrows; r += 32) {
                float e = __expf(sp[r * 8 + w]);
                sp[r * 8 + w] = e;
                s += e;
            }
#pragma unroll
            for (int off = 16; off > 0; off >>= 1)
                s += __shfl_down_sync(0xffffffffu, s, off);
            if (l == 0) g_psum[(b * NCHUNK + chunk) * TT + w] = s;
        }
        __syncthreads();

        // ---- phase C: stream V rows: copy + p*V ----
        const float4* vin = cp ? (const float4*)(cache_v + ((size_t)b * SPAST + s0) * CC)
                               : (const float4*)(out_v + ((size_t)b * SS + s0) * CC);
        float4* vout = (float4*)(out_v + ((size_t)b * SS + s0) * CC);

        float4 acc[8];
#pragma unroll
        for (int t = 0; t < 8; t++) acc[t] = make_float4(0.f, 0.f, 0.f, 0.f);

#pragma unroll 4
        for (int i = 0; i < nrows; i += 4) {
            float4 vr[4];
            vr[0] = __ldcs(vin + (size_t)(i + 0) * 256 + tid);
            vr[1] = __ldcs(vin + (size_t)(i + 1) * 256 + tid);
            vr[2] = __ldcs(vin + (size_t)(i + 2) * 256 + tid);
            vr[3] = __ldcs(vin + (size_t)(i + 3) * 256 + tid);
            if (cp) {
                __stcs(vout + (size_t)(i + 0) * 256 + tid, vr[0]);
                __stcs(vout + (size_t)(i + 1) * 256 + tid, vr[1]);
                __stcs(vout + (size_t)(i + 2) * 256 + tid, vr[2]);
                __stcs(vout + (size_t)(i + 3) * 256 + tid, vr[3]);
            }
#pragma unroll
            for (int r = 0; r < 4; r++) {
                float4 vv = vr[r];
                float4 p0 = sp4[(i + r) * 2], p1 = sp4[(i + r) * 2 + 1];
                acc[0].x += vv.x * p0.x; acc[0].y += vv.y * p0.x; acc[0].z += vv.z * p0.x; acc[0].w += vv.w * p0.x;
                acc[1].x += vv.x * p0.y; acc[1].y += vv.y * p0.y; acc[1].z += vv.z * p0.y; acc[1].w += vv.w * p0.y;
                acc[2].x += vv.x * p0.z; acc[2].y += vv.y * p0.z; acc[2].z += vv.z * p0.z; acc[2].w += vv.w * p0.z;
                acc[3].x += vv.x * p0.w; acc[3].y += vv.y * p0.w; acc[3].z += vv.z * p0.w; acc[3].w += vv.w * p0.w;
                acc[4].x += vv.x * p1.x; acc[4].y += vv.y * p1.x; acc[4].z += vv.z * p1.x; acc[4].w += vv.w * p1.x;
                acc[5].x += vv.x * p1.y; acc[5].y += vv.y * p1.y; acc[5].z += vv.z * p1.y; acc[5].w += vv.w * p1.y;
                acc[6].x += vv.x * p1.z; acc[6].y += vv.y * p1.z; acc[6].z += vv.z * p1.z; acc[6].w += vv.w * p1.z;
                acc[7].x += vv.x * p1.w; acc[7].y += vv.y * p1.w; acc[7].z += vv.z * p1.w; acc[7].w += vv.w * p1.w;
            }
        }
        float4* dst = (float4*)(g_part + ((size_t)(b * NCHUNK + chunk) * TT) * CC);
#pragma unroll
        for (int t = 0; t < 8; t++) dst[t * 256 + tid] = acc[t];

        __syncthreads();   // protect sp / s_pos before next iteration
    }
}

// ---------------- reduce chunk partials -> normalized ctx (float4) ----------
__global__ void k_reduce() {
    int g4 = blockIdx.x * 256 + threadIdx.x;   // 0..32767
    int row = g4 >> 8;
    int c = (g4 & 255) * 4;
    int b = row >> 3, t = row & 7;
    float S = 0.f;
#pragma unroll
    for (int ch = 0; ch < NCHUNK; ch++)
        S += g_psum[(b * NCHUNK + ch) * TT + t];
    float4 s = make_float4(0.f, 0.f, 0.f, 0.f);
#pragma unroll
    for (int ch = 0; ch < NCHUNK; ch++) {
        float4 p = *(const float4*)&g_part[((size_t)(b * NCHUNK + ch) * TT + t) * CC + c];
        s.x += p.x; s.y += p.y; s.z += p.z; s.w += p.w;
    }
    float inv = 1.0f / S;
    *(float4*)&g_ctx[(size_t)row * CC + c] =
        make_float4(s.x * inv, s.y * inv, s.z * inv, s.w * inv);
}

// ---------------- launch ----------------
extern "C" void kernel_launch(void* const* d_in, const int* in_sizes, int n_in,
                              void* d_out, int out_size) {
    const float* x       = (const float*)d_in[0];
    const float* cache_k = (const float*)d_in[1];
    const float* cache_v = (const float*)d_in[2];
    const float* w_qkv   = (const float*)d_in[3];
    const float* b_qkv   = (const float*)d_in[4];
    const float* w_out   = (const float*)d_in[5];
    const float* b_out   = (const float*)d_in[6];

    float* out_o = (float*)d_out;
    float* out_k = out_o + (size_t)BT * CC;
    float* out_v = out_k + (size_t)BB * SS * CC;

    k_reset<<<1, 1>>>();
    k_gemm<3072, 0><<<dim3(48, 2, KSPLIT), 256>>>(x, w_qkv);
    k_qkv_red<<<384, 256>>>(b_qkv, out_k, out_v);
    k_attn<<<ATTN_GRID, 256>>>(cache_k, cache_v, out_k, out_v);
    k_reduce<<<128, 256>>>();
    k_gemm<1024, 1><<<dim3(16, 2, KSPLIT), 256>>>(nullptr, w_out);
    k_out_red<<<128, 256>>>(b_out, out_o);
}